// round 5
// baseline (speedup 1.0000x reference)
#include <cuda_runtime.h>
#include <math.h>

#define BATCH 8
#define C 256
#define HWN 4096
#define NG 256
#define BNC (BATCH*HWN*C)
#define GNC (BATCH*NG*C)
#define NCH 64
#define CHL 64
#define BK 32
#define LDSP 68

// ---------------- scratch (device globals; no allocation allowed) ----------
__device__ float g_seq[BNC], g_u[BNC], g_a[BNC], g_b[BNC], g_o[BNC];
__device__ float g_yf[BNC], g_yb[BNC], g_y[BNC], g_ygs[BNC];
__device__ float g_vmap[BNC], g_v[BNC], g_z[BNC], g_uout[BNC];
__device__ float g_posF[HWN*C], g_posG[NG*C];
__device__ float g_ctx[BATCH*C], g_ctxg[BATCH*C];
__device__ float g_cvec[3*BATCH*C], g_cvecg[3*BATCH*C];
__device__ float g_cp[BATCH*16*C];
__device__ float g_Ag[BATCH*NCH*C], g_Bf[BATCH*NCH*C], g_Bb[BATCH*NCH*C];
__device__ float g_If[BATCH*NCH*C], g_Ib[BATCH*NCH*C];
__device__ float g_sg[GNC], g_ug[GNC], g_ga[GNC], g_gb[GNC], g_go[GNC], g_yg[GNC];

__device__ __forceinline__ float sigm(float x){ return 1.f/(1.f+expf(-x)); }

// ---------------- transpose: [B,C,N] -> [B,N,C] ----------------------------
__global__ void tpose(const float* __restrict__ in, float* __restrict__ out, int N){
    __shared__ float t[32][33];
    int b = blockIdx.z, n0 = blockIdx.x*32, c0 = blockIdx.y*32;
    int tx = threadIdx.x, ty = threadIdx.y;
    for (int i = 0; i < 32; i += 8)
        t[ty+i][tx] = in[((size_t)(b*C + c0+ty+i))*N + n0 + tx];
    __syncthreads();
    for (int i = 0; i < 32; i += 8)
        out[((size_t)(b*N + n0+ty+i))*C + c0 + tx] = t[tx][ty+i];
}

// out[B,C,N] = x[B,C,N] + t[B,N,C]^T
__global__ void tpose_add(const float* __restrict__ t, const float* __restrict__ x,
                          float* __restrict__ out){
    __shared__ float s[32][33];
    int b = blockIdx.z, n0 = blockIdx.x*32, c0 = blockIdx.y*32;
    int tx = threadIdx.x, ty = threadIdx.y;
    for (int i = 0; i < 32; i += 8)
        s[ty+i][tx] = t[((size_t)(b*HWN + n0+ty+i))*C + c0 + tx];
    __syncthreads();
    for (int i = 0; i < 32; i += 8) {
        size_t o = ((size_t)(b*C + c0+ty+i))*HWN + n0 + tx;
        out[o] = x[o] + s[tx][ty+i];
    }
}

// ---------------- GEMM: A from up to 3 row-major [M,256] segments ----------
// out[m,c] = sum_k A[m,k]*W[k,c] (+bias[c]) (+addrow[(m&nmask),c]) (+addb[(m>>bshift),c])
// epi: 0 raw; 1: s=sig(r), out=s*E0+(1-s)*E1; 2: s=sig(r), out=E0+s*E1
__global__ void __launch_bounds__(256) gemm(
    const float* __restrict__ A0, const float* __restrict__ A1, const float* __restrict__ A2,
    int nseg, const float* __restrict__ W, const float* __restrict__ bias,
    const float* __restrict__ addrow, int nmask,
    const float* __restrict__ addb, int bshift,
    const float* __restrict__ E0, const float* __restrict__ E1,
    float* __restrict__ out, int epi)
{
    __shared__ __align__(16) float As[BK*LDSP];
    __shared__ __align__(16) float Bs[BK*LDSP];
    int m0 = blockIdx.y * 64, c0 = blockIdx.x * 64;
    int t = threadIdx.x;
    int tx = t & 15, ty = t >> 4;
    int mA = t >> 2, kq = (t & 3) * 8;
    int klB = t >> 3, cq = (t & 7) * 8;
    float acc[4][4] = {};
    int K = nseg << 8;
    for (int k0 = 0; k0 < K; k0 += BK) {
        int kg = k0 + kq;
        const float* seg = (kg < 256) ? A0 : (kg < 512 ? A1 : A2);
        const float* pa = seg + (size_t)(m0 + mA) * C + (kg & 255);
        float4 a0 = *(const float4*)pa;
        float4 a1 = *(const float4*)(pa + 4);
        As[(kq+0)*LDSP+mA] = a0.x; As[(kq+1)*LDSP+mA] = a0.y;
        As[(kq+2)*LDSP+mA] = a0.z; As[(kq+3)*LDSP+mA] = a0.w;
        As[(kq+4)*LDSP+mA] = a1.x; As[(kq+5)*LDSP+mA] = a1.y;
        As[(kq+6)*LDSP+mA] = a1.z; As[(kq+7)*LDSP+mA] = a1.w;
        const float* pb = W + (size_t)(k0 + klB) * C + c0 + cq;
        *(float4*)(Bs + klB*LDSP + cq)     = *(const float4*)pb;
        *(float4*)(Bs + klB*LDSP + cq + 4) = *(const float4*)(pb + 4);
        __syncthreads();
        #pragma unroll
        for (int kk = 0; kk < BK; kk++) {
            float4 av = *(const float4*)(As + kk*LDSP + ty*4);
            float4 bv = *(const float4*)(Bs + kk*LDSP + tx*4);
            acc[0][0]+=av.x*bv.x; acc[0][1]+=av.x*bv.y; acc[0][2]+=av.x*bv.z; acc[0][3]+=av.x*bv.w;
            acc[1][0]+=av.y*bv.x; acc[1][1]+=av.y*bv.y; acc[1][2]+=av.y*bv.z; acc[1][3]+=av.y*bv.w;
            acc[2][0]+=av.z*bv.x; acc[2][1]+=av.z*bv.y; acc[2][2]+=av.z*bv.z; acc[2][3]+=av.z*bv.w;
            acc[3][0]+=av.w*bv.x; acc[3][1]+=av.w*bv.y; acc[3][2]+=av.w*bv.z; acc[3][3]+=av.w*bv.w;
        }
        __syncthreads();
    }
    float4 bv4 = make_float4(0.f,0.f,0.f,0.f);
    if (bias) {
        float4 q = *(const float4*)(bias + c0 + tx*4);
        bv4.x+=q.x; bv4.y+=q.y; bv4.z+=q.z; bv4.w+=q.w;
    }
    if (addb) {
        float4 q = *(const float4*)(addb + (m0>>bshift)*C + c0 + tx*4);
        bv4.x+=q.x; bv4.y+=q.y; bv4.z+=q.z; bv4.w+=q.w;
    }
    #pragma unroll
    for (int i = 0; i < 4; i++) {
        int m = m0 + ty*4 + i;
        size_t off = (size_t)m * C + c0 + tx*4;
        float4 r;
        r.x = acc[i][0]+bv4.x; r.y = acc[i][1]+bv4.y; r.z = acc[i][2]+bv4.z; r.w = acc[i][3]+bv4.w;
        if (addrow) {
            float4 p = *(const float4*)(addrow + (size_t)(m & nmask)*C + c0 + tx*4);
            r.x+=p.x; r.y+=p.y; r.z+=p.z; r.w+=p.w;
        }
        if (epi == 0) { *(float4*)(out + off) = r; continue; }
        float4 e0 = *(const float4*)(E0 + off);
        float4 e1 = *(const float4*)(E1 + off);
        float4 s = make_float4(sigm(r.x), sigm(r.y), sigm(r.z), sigm(r.w));
        float4 o4;
        if (epi == 1) {
            o4.x = s.x*e0.x+(1.f-s.x)*e1.x; o4.y = s.y*e0.y+(1.f-s.y)*e1.y;
            o4.z = s.z*e0.z+(1.f-s.z)*e1.z; o4.w = s.w*e0.w+(1.f-s.w)*e1.w;
        } else {
            o4.x = e0.x+s.x*e1.x; o4.y = e0.y+s.y*e1.y;
            o4.z = e0.z+s.z*e1.z; o4.w = e0.w+s.w*e1.w;
        }
        *(float4*)(out + off) = o4;
    }
}

// ---------------- positional embeddings ------------------------------------
__global__ void posF_kernel(const float* __restrict__ pf){
    int n = blockIdx.x, c = threadIdx.x;
    int oy = n >> 6, ox = n & 63;
    float sy = oy*0.5f - 0.25f, sx = ox*0.5f - 0.25f;
    int y0 = (int)floorf(sy); float fy = sy - (float)y0;
    int x0 = (int)floorf(sx); float fx = sx - (float)x0;
    int y0c = y0<0?0:y0, y1c = (y0+1)>31?31:(y0+1);
    int x0c = x0<0?0:x0, x1c = (x0+1)>31?31:(x0+1);
    const float* p = pf + c*1024;
    float v00=p[y0c*32+x0c], v01=p[y0c*32+x1c], v10=p[y1c*32+x0c], v11=p[y1c*32+x1c];
    g_posF[n*C+c] = (1.f-fy)*((1.f-fx)*v00+fx*v01) + fy*((1.f-fx)*v10+fx*v11);
}

__global__ void posG_kernel(const float* __restrict__ pg){
    int n = blockIdx.x, c = threadIdx.x;
    int oy = n >> 4, ox = n & 15;
    const float wt[4] = {0.25f, 0.75f, 0.75f, 0.25f};
    float wy[4], wx[4]; int iy[4], ix[4];
    float swy = 0.f, swx = 0.f;
    #pragma unroll
    for (int r = 0; r < 4; r++) {
        int y = 2*oy - 1 + r;
        if (y >= 0 && y < 32) { iy[r]=y; wy[r]=wt[r]; swy+=wt[r]; } else { iy[r]=0; wy[r]=0.f; }
        int x = 2*ox - 1 + r;
        if (x >= 0 && x < 32) { ix[r]=x; wx[r]=wt[r]; swx+=wt[r]; } else { ix[r]=0; wx[r]=0.f; }
    }
    const float* p = pg + c*1024;
    float acc = 0.f;
    #pragma unroll
    for (int ry = 0; ry < 4; ry++)
        #pragma unroll
        for (int rx = 0; rx < 4; rx++)
            acc += wy[ry]*wx[rx]*p[iy[ry]*32 + ix[rx]];
    g_posG[n*C+c] = acc / (swy*swx);
}

// ---------------- pooled-LN context ----------------------------------------
__global__ void ctx_partial(){
    int c = threadIdx.x, s = blockIdx.x, b = blockIdx.y;
    size_t base = ((size_t)b*HWN + s*256)*C + c;
    float acc = 0.f;
    for (int i = 0; i < 256; i++) acc += g_u[base + (size_t)i*C];
    g_cp[(b*16+s)*C + c] = acc;
}

__global__ void ctx_final(const float* __restrict__ lng, const float* __restrict__ lnb){
    __shared__ float red[256];
    int b = blockIdx.x, c = threadIdx.x;
    float m = 0.f;
    for (int s = 0; s < 16; s++) m += g_cp[(b*16+s)*C + c];
    m *= (1.f/(float)HWN);
    red[c] = m; __syncthreads();
    for (int s = 128; s > 0; s >>= 1) { if (c < s) red[c] += red[c+s]; __syncthreads(); }
    float mu = red[0] * (1.f/(float)C); __syncthreads();
    float d = m - mu;
    red[c] = d*d; __syncthreads();
    for (int s = 128; s > 0; s >>= 1) { if (c < s) red[c] += red[c+s]; __syncthreads(); }
    float var = red[0] * (1.f/(float)C);
    g_ctx[b*C+c] = d * rsqrtf(var + 1e-5f) * lng[c] + lnb[c];
}

__global__ void ctxg_kernel(const float* __restrict__ lng, const float* __restrict__ lnb){
    __shared__ float red[256];
    int b = blockIdx.x, c = threadIdx.x;
    float m = 0.f;
    for (int n = 0; n < NG; n++) m += g_ug[((size_t)b*NG + n)*C + c];
    m *= (1.f/(float)NG);
    red[c] = m; __syncthreads();
    for (int s = 128; s > 0; s >>= 1) { if (c < s) red[c] += red[c+s]; __syncthreads(); }
    float mu = red[0] * (1.f/(float)C); __syncthreads();
    float d = m - mu;
    red[c] = d*d; __syncthreads();
    for (int s = 128; s > 0; s >>= 1) { if (c < s) red[c] += red[c+s]; __syncthreads(); }
    float var = red[0] * (1.f/(float)C);
    g_ctxg[b*C+c] = d * rsqrtf(var + 1e-5f) * lng[c] + lnb[c];
}

// cv[gate,b,c] = bias_g[c] + sum_k ctx[b,k]*Wg[(256+k),c]
__global__ void cvec_kernel(const float* __restrict__ ctx,
    const float* __restrict__ Wf, const float* __restrict__ Ww, const float* __restrict__ Wo,
    const float* __restrict__ bf, const float* __restrict__ bw, const float* __restrict__ bo,
    float* __restrict__ cv){
    __shared__ float cs[256];
    int b = blockIdx.x, gate = blockIdx.y, c = threadIdx.x;
    cs[c] = ctx[b*C+c]; __syncthreads();
    const float* Wg = (gate==0 ? Wf : (gate==1 ? Ww : Wo)) + 256*C;
    const float* bg = (gate==0 ? bf : (gate==1 ? bw : bo));
    float acc = bg[c];
    #pragma unroll 4
    for (int k = 0; k < 256; k++) acc += cs[k] * Wg[k*C + c];
    cv[(gate*BATCH + b)*C + c] = acc;
}

// ---------------- gate pointwise -------------------------------------------
__global__ void abc_kernel(float* __restrict__ da, float* __restrict__ db,
                           float* __restrict__ dc, const float* __restrict__ u, int n){
    int i = blockIdx.x*256 + threadIdx.x;
    if (i < n) {
        float a = 1.f/(1.f + expf(da[i]));   // exp(-softplus(x)) == sigmoid(-x)
        float g = sigm(db[i]);
        da[i] = a;
        db[i] = (1.f - a) * g * u[i];
        dc[i] = sigm(dc[i]);
    }
}

// ---------------- chunked bidirectional scan -------------------------------
__global__ void scan_p1(){
    int c = threadIdx.x, k = blockIdx.x % NCH, b = blockIdx.x / NCH;
    size_t base = ((size_t)b*HWN + k*CHL)*C + c;
    float P = 1.f, Sf = 0.f, Bb = 0.f;
    for (int i = 0; i < CHL; i++) {
        float av = g_a[base + (size_t)i*C], bv = g_b[base + (size_t)i*C];
        Sf = av*Sf + bv;
        Bb += P*bv;
        P *= av;
    }
    int o = (b*NCH + k)*C + c;
    g_Ag[o] = P; g_Bf[o] = Sf; g_Bb[o] = Bb;
}

__global__ void scan_p2(){
    int t = blockIdx.x*256 + threadIdx.x;
    int b = t >> 8, c = t & 255;
    float S = 0.f;
    for (int k = 0; k < NCH; k++) {
        int o = (b*NCH + k)*C + c;
        g_If[o] = S;
        S = g_Ag[o]*S + g_Bf[o];
    }
    S = 0.f;
    for (int k = NCH-1; k >= 0; k--) {
        int o = (b*NCH + k)*C + c;
        g_Ib[o] = S;
        S = g_Ag[o]*S + g_Bb[o];
    }
}

__global__ void scan_p3(){
    int c = threadIdx.x, k = blockIdx.x % NCH, b = blockIdx.x / NCH;
    size_t base = ((size_t)b*HWN + k*CHL)*C + c;
    int o = (b*NCH + k)*C + c;
    float s = g_If[o];
    for (int i = 0; i < CHL; i++) {
        size_t idx = base + (size_t)i*C;
        float av = g_a[idx], bv = g_b[idx], ov = g_o[idx], uv = g_u[idx];
        s = av*s + bv;
        g_yf[idx] = ov*s + (1.f - ov)*uv;
    }
    s = g_Ib[o];
    for (int i = CHL-1; i >= 0; i--) {
        size_t idx = base + (size_t)i*C;
        float av = g_a[idx], bv = g_b[idx], ov = g_o[idx], uv = g_u[idx];
        s = av*s + bv;
        g_yb[idx] = ov*s + (1.f - ov)*uv;
    }
}

// ---------------- global branch --------------------------------------------
__global__ void pool_kernel(const float* __restrict__ x){
    int bc = blockIdx.x, t = threadIdx.x;
    int b = bc >> 8, c = bc & 255;
    int gy = t >> 4, gx = t & 15;
    const float* xp = x + (size_t)bc*HWN + (gy*4)*64 + gx*4;
    float s = 0.f;
    #pragma unroll
    for (int iy = 0; iy < 4; iy++)
        #pragma unroll
        for (int ix = 0; ix < 4; ix++)
            s += xp[iy*64 + ix];
    g_sg[((size_t)b*NG + t)*C + c] = s * 0.0625f;
}

__global__ void scan_g(){
    int b = blockIdx.x, c = threadIdx.x;
    float s = 0.f;
    #pragma unroll 4
    for (int n = 0; n < NG; n++) {
        size_t i = ((size_t)b*NG + n)*C + c;
        float a = g_ga[i], bb = g_gb[i], o = g_go[i], u = g_ug[i];
        s = a*s + bb;
        g_yg[i] = o*s + (1.f - o)*u;
    }
}

__global__ void upsample_kernel(){
    int n = blockIdx.x, b = blockIdx.y, c = threadIdx.x;
    int oy = n >> 6, ox = n & 63;
    float sy = oy*0.25f - 0.375f, sx = ox*0.25f - 0.375f;
    int y0 = (int)floorf(sy); float fy = sy - (float)y0;
    int x0 = (int)floorf(sx); float fx = sx - (float)x0;
    int y0c = y0<0?0:y0, y1c = (y0+1)>15?15:(y0+1);
    int x0c = x0<0?0:x0, x1c = (x0+1)>15?15:(x0+1);
    const float* Y = g_yg + (size_t)b*NG*C + c;
    float v00=Y[(y0c*16+x0c)*C], v01=Y[(y0c*16+x1c)*C];
    float v10=Y[(y1c*16+x0c)*C], v11=Y[(y1c*16+x1c)*C];
    g_ygs[((size_t)b*HWN + n)*C + c] =
        (1.f-fy)*((1.f-fx)*v00+fx*v01) + fy*((1.f-fx)*v10+fx*v11);
}

// ---------------- depthwise conv -------------------------------------------
__global__ void dwconv(const float* __restrict__ x, const float* __restrict__ w,
                       const float* __restrict__ bias){
    int bc = blockIdx.x;
    int c = bc & 255;
    int h = blockIdx.y*4 + threadIdx.y;
    int wq = threadIdx.x;
    const float* xp = x + (size_t)bc*HWN;
    float kk[9];
    #pragma unroll
    for (int i = 0; i < 9; i++) kk[i] = w[c*9 + i];
    float s = bias[c];
    #pragma unroll
    for (int dy = -1; dy <= 1; dy++) {
        int yy = h + dy;
        if (yy < 0 || yy > 63) continue;
        #pragma unroll
        for (int dx = -1; dx <= 1; dx++) {
            int xx = wq + dx;
            if (xx < 0 || xx > 63) continue;
            s += xp[yy*64 + xx] * kk[(dy+1)*3 + (dx+1)];
        }
    }
    g_vmap[(size_t)bc*HWN + h*64 + wq] = s;
}

// ---------------- host ------------------------------------------------------
static float* sym(const void* s){ void* p = 0; cudaGetSymbolAddress(&p, s); return (float*)p; }

extern "C" void kernel_launch(void* const* d_in, const int* in_sizes, int n_in,
                              void* d_out, int out_size)
{
    const float* x    = (const float*)d_in[0];
    const float* Wt   = (const float*)d_in[1];
    const float* bt   = (const float*)d_in[2];
    const float* pos_fine = (const float*)d_in[3];
    const float* pos_glob = (const float*)d_in[4];
    const float* ln_g = (const float*)d_in[5];
    const float* ln_b = (const float*)d_in[6];
    const float* Wf   = (const float*)d_in[7];
    const float* bf   = (const float*)d_in[8];
    const float* Ww   = (const float*)d_in[9];
    const float* bw   = (const float*)d_in[10];
    const float* Wo   = (const float*)d_in[11];
    const float* bo   = (const float*)d_in[12];
    const float* Wr   = (const float*)d_in[13];
    const float* br   = (const float*)d_in[14];
    const float* Wgi  = (const float*)d_in[15];
    const float* bgi  = (const float*)d_in[16];
    const float* dww  = (const float*)d_in[17];
    const float* dwb  = (const float*)d_in[18];
    const float* Wl   = (const float*)d_in[19];
    const float* bl   = (const float*)d_in[20];
    const float* Wlf  = (const float*)d_in[21];
    const float* blf  = (const float*)d_in[22];
    const float* Wout = (const float*)d_in[23];
    const float* bout = (const float*)d_in[24];
    float* out = (float*)d_out;

    float* dseq  = sym(g_seq);  float* du   = sym(g_u);
    float* da    = sym(g_a);    float* db_  = sym(g_b);   float* do_  = sym(g_o);
    float* dyf   = sym(g_yf);   float* dyb  = sym(g_yb);  float* dy   = sym(g_y);
    float* dygs  = sym(g_ygs);  float* dvmap= sym(g_vmap);
    float* dv    = sym(g_v);    float* dz   = sym(g_z);   float* duout= sym(g_uout);
    float* dposF = sym(g_posF); float* dposG= sym(g_posG);
    float* dctx  = sym(g_ctx);  float* dctxg= sym(g_ctxg);
    float* dcvec = sym(g_cvec); float* dcvecg=sym(g_cvecg);
    float* dsg   = sym(g_sg);   float* dug  = sym(g_ug);
    float* dga   = sym(g_ga);   float* dgb  = sym(g_gb);  float* dgo  = sym(g_go);

    dim3 tb(32, 8);
    dim3 tg(128, 8, BATCH);
    dim3 gF(4, BATCH*HWN/64);   // fine GEMMs: M = 32768
    dim3 gG(4, BATCH*NG/64);    // global GEMMs: M = 2048

    // fine u = seq@Wt + bt + posF
    tpose<<<tg, tb>>>(x, dseq, HWN);
    posF_kernel<<<HWN, 256>>>(pos_fine);
    posG_kernel<<<NG, 256>>>(pos_glob);
    gemm<<<gF,256>>>(dseq,0,0,1, Wt, bt, dposF,4095, 0,0, 0,0, du, 0);

    // context and gates
    ctx_partial<<<dim3(16,BATCH), 256>>>();
    ctx_final<<<BATCH, 256>>>(ln_g, ln_b);
    cvec_kernel<<<dim3(BATCH,3), 256>>>(dctx, Wf,Ww,Wo, bf,bw,bo, dcvec);
    gemm<<<gF,256>>>(du,0,0,1, Wf, 0, 0,0, dcvec,            12, 0,0, da,  0);
    gemm<<<gF,256>>>(du,0,0,1, Ww, 0, 0,0, dcvec+BATCH*C,    12, 0,0, db_, 0);
    gemm<<<gF,256>>>(du,0,0,1, Wo, 0, 0,0, dcvec+2*BATCH*C,  12, 0,0, do_, 0);
    abc_kernel<<<BNC/256, 256>>>(da, db_, do_, du, BNC);

    // bidirectional scan (gates are flip-invariant)
    scan_p1<<<BATCH*NCH, 256>>>();
    scan_p2<<<8, 256>>>();
    scan_p3<<<BATCH*NCH, 256>>>();
    // y = sigmoid([u,yf,yb]@Wr+br)*yf + (1-.)*yb
    gemm<<<gF,256>>>(du,dyf,dyb,3, Wr, br, 0,0, 0,0, dyf,dyb, dy, 1);

    // global branch
    pool_kernel<<<BATCH*C, 256>>>(x);
    gemm<<<gG,256>>>(dsg,0,0,1, Wt, bt, dposG,255, 0,0, 0,0, dug, 0);
    ctxg_kernel<<<BATCH, 256>>>(ln_g, ln_b);
    cvec_kernel<<<dim3(BATCH,3), 256>>>(dctxg, Wf,Ww,Wo, bf,bw,bo, dcvecg);
    gemm<<<gG,256>>>(dug,0,0,1, Wf, 0, 0,0, dcvecg,           8, 0,0, dga, 0);
    gemm<<<gG,256>>>(dug,0,0,1, Ww, 0, 0,0, dcvecg+BATCH*C,   8, 0,0, dgb, 0);
    gemm<<<gG,256>>>(dug,0,0,1, Wo, 0, 0,0, dcvecg+2*BATCH*C, 8, 0,0, dgo, 0);
    abc_kernel<<<GNC/256, 256>>>(dga, dgb, dgo, dug, GNC);
    scan_g<<<BATCH, 256>>>();
    upsample_kernel<<<dim3(HWN,BATCH), 256>>>();

    // z = y + sigmoid([y,ygs,u]@Wgi+bgi)*ygs
    gemm<<<gF,256>>>(dy,dygs,du,3, Wgi, bgi, 0,0, 0,0, dy,dygs, dz, 2);

    // local branch: v = dwconv(x)^T @ Wl + bl ; uout = eta*v + (1-eta)*z
    dwconv<<<dim3(BATCH*C,16), dim3(64,4)>>>(x, dww, dwb);
    tpose<<<tg, tb>>>(dvmap, dseq, HWN);
    gemm<<<gF,256>>>(dseq,0,0,1, Wl, bl, 0,0, 0,0, 0,0, dv, 0);
    gemm<<<gF,256>>>(dv,dz,0,2, Wlf, blf, 0,0, 0,0, dv,dz, duout, 1);

    // out = x + (uout@Wout + bout)^T
    gemm<<<gF,256>>>(duout,0,0,1, Wout, bout, 0,0, 0,0, 0,0, du, 0);
    tpose_add<<<tg, tb>>>(du, x, out);
}

// round 10
// speedup vs baseline: 1.1019x; 1.1019x over previous
#include <cuda_runtime.h>
#include <math.h>

#define BATCH 8
#define C 256
#define HWN 4096
#define NG 256
#define BNC (BATCH*HWN*C)
#define GNC (BATCH*NG*C)
#define NCH 64
#define CHL 64
#define BM 128
#define BN 128
#define BKK 16
#define SST 132

// ---------------- scratch (device globals; no allocation allowed) ----------
__device__ float g_seq[BNC], g_u[BNC], g_a[BNC], g_b[BNC], g_o[BNC];
__device__ float g_yf[BNC], g_yb[BNC], g_y[BNC], g_ygs[BNC];
__device__ float g_vmap[BNC], g_v[BNC], g_z[BNC], g_uout[BNC];
__device__ float g_posF[HWN*C], g_posG[NG*C];
__device__ float g_ctx[BATCH*C], g_ctxg[BATCH*C];
__device__ float g_cvec[3*BATCH*C], g_cvecg[3*BATCH*C];
__device__ float g_cp[BATCH*16*C];
__device__ float g_Ag[BATCH*NCH*C], g_Bf[BATCH*NCH*C], g_Bb[BATCH*NCH*C];
__device__ float g_If[BATCH*NCH*C], g_Ib[BATCH*NCH*C];
__device__ float g_sg[GNC], g_ug[GNC], g_ga[GNC], g_gb[GNC], g_go[GNC], g_yg[GNC];

__device__ __forceinline__ float sigm(float x){ return 1.f/(1.f+expf(-x)); }

// ---------------- transpose: [B,C,N] -> [B,N,C] ----------------------------
__global__ void tpose(const float* __restrict__ in, float* __restrict__ out, int N){
    __shared__ float t[32][33];
    int b = blockIdx.z, n0 = blockIdx.x*32, c0 = blockIdx.y*32;
    int tx = threadIdx.x, ty = threadIdx.y;
    for (int i = 0; i < 32; i += 8)
        t[ty+i][tx] = in[((size_t)(b*C + c0+ty+i))*N + n0 + tx];
    __syncthreads();
    for (int i = 0; i < 32; i += 8)
        out[((size_t)(b*N + n0+ty+i))*C + c0 + tx] = t[tx][ty+i];
}

// out[B,C,N] = x[B,C,N] + t[B,N,C]^T
__global__ void tpose_add(const float* __restrict__ t, const float* __restrict__ x,
                          float* __restrict__ out){
    __shared__ float s[32][33];
    int b = blockIdx.z, n0 = blockIdx.x*32, c0 = blockIdx.y*32;
    int tx = threadIdx.x, ty = threadIdx.y;
    for (int i = 0; i < 32; i += 8)
        s[ty+i][tx] = t[((size_t)(b*HWN + n0+ty+i))*C + c0 + tx];
    __syncthreads();
    for (int i = 0; i < 32; i += 8) {
        size_t o = ((size_t)(b*C + c0+ty+i))*HWN + n0 + tx;
        out[o] = x[o] + s[tx][ty+i];
    }
}

// ---------------- GEMM: 128x128 tile, 8x8 microtile, BK=16 -----------------
// A from up to 3 row-major [M,256] segments.
// out[m,c] = sum_k A[m,k]*W[k,c] (+bias[c]) (+addrow[(m&nmask),c]) (+addb[(m>>bshift),c])
// epi: 0 raw; 1: s=sig(r), out=s*E0+(1-s)*E1; 2: s=sig(r), out=E0+s*E1
__global__ void __launch_bounds__(256) gemm(
    const float* __restrict__ A0, const float* __restrict__ A1, const float* __restrict__ A2,
    int nseg, const float* __restrict__ W, const float* __restrict__ bias,
    const float* __restrict__ addrow, int nmask,
    const float* __restrict__ addb, int bshift,
    const float* __restrict__ E0, const float* __restrict__ E1,
    float* __restrict__ out, int epi)
{
    __shared__ __align__(16) float As[BKK*SST];   // As[k][m]
    __shared__ __align__(16) float Bs[BKK*SST];   // Bs[k][c]
    int m0 = blockIdx.y * BM, c0 = blockIdx.x * BN;
    int t = threadIdx.x;
    int tx = t & 15, ty = t >> 4;
    int arow = t >> 1, akq = (t & 1) * 8;         // A: 2 threads/row, 8 k each
    int brow = t >> 4, bcq = tx * 8;              // B: 16 threads/row, 8 c each
    float acc[8][8] = {};
    int K = nseg << 8;

    float4 a0, a1, b0, b1;
    {
        const float* pa = A0 + (size_t)(m0 + arow) * C + akq;
        a0 = *(const float4*)pa; a1 = *(const float4*)(pa + 4);
        const float* pb = W + (size_t)brow * C + c0 + bcq;
        b0 = *(const float4*)pb; b1 = *(const float4*)(pb + 4);
    }

    for (int k0 = 0; k0 < K; k0 += BKK) {
        // stage regs -> smem (A transposed)
        As[(akq+0)*SST + arow] = a0.x; As[(akq+1)*SST + arow] = a0.y;
        As[(akq+2)*SST + arow] = a0.z; As[(akq+3)*SST + arow] = a0.w;
        As[(akq+4)*SST + arow] = a1.x; As[(akq+5)*SST + arow] = a1.y;
        As[(akq+6)*SST + arow] = a1.z; As[(akq+7)*SST + arow] = a1.w;
        *(float4*)(Bs + brow*SST + bcq)     = b0;
        *(float4*)(Bs + brow*SST + bcq + 4) = b1;
        __syncthreads();
        if (k0 + BKK < K) {
            int kg = k0 + BKK + akq;
            const float* seg = (kg < 256) ? A0 : (kg < 512 ? A1 : A2);
            const float* pa = seg + (size_t)(m0 + arow) * C + (kg & 255);
            a0 = *(const float4*)pa; a1 = *(const float4*)(pa + 4);
            const float* pb = W + (size_t)(k0 + BKK + brow) * C + c0 + bcq;
            b0 = *(const float4*)pb; b1 = *(const float4*)(pb + 4);
        }
        #pragma unroll
        for (int kk = 0; kk < BKK; kk++) {
            float4 av0 = *(const float4*)(As + kk*SST + ty*4);
            float4 av1 = *(const float4*)(As + kk*SST + 64 + ty*4);
            float4 bv0 = *(const float4*)(Bs + kk*SST + tx*4);
            float4 bv1 = *(const float4*)(Bs + kk*SST + 64 + tx*4);
            float ar[8] = {av0.x,av0.y,av0.z,av0.w, av1.x,av1.y,av1.z,av1.w};
            float br[8] = {bv0.x,bv0.y,bv0.z,bv0.w, bv1.x,bv1.y,bv1.z,bv1.w};
            #pragma unroll
            for (int i = 0; i < 8; i++)
                #pragma unroll
                for (int j = 0; j < 8; j++)
                    acc[i][j] += ar[i] * br[j];
        }
        __syncthreads();
    }

    float4 bb[2] = {make_float4(0,0,0,0), make_float4(0,0,0,0)};
    if (bias) {
        #pragma unroll
        for (int j = 0; j < 2; j++) {
            float4 q = *(const float4*)(bias + c0 + j*64 + tx*4);
            bb[j].x+=q.x; bb[j].y+=q.y; bb[j].z+=q.z; bb[j].w+=q.w;
        }
    }
    if (addb) {
        #pragma unroll
        for (int j = 0; j < 2; j++) {
            float4 q = *(const float4*)(addb + (m0>>bshift)*C + c0 + j*64 + tx*4);
            bb[j].x+=q.x; bb[j].y+=q.y; bb[j].z+=q.z; bb[j].w+=q.w;
        }
    }
    #pragma unroll
    for (int i = 0; i < 8; i++) {
        int m = m0 + ((i < 4) ? (ty*4 + i) : (60 + ty*4 + i));
        #pragma unroll
        for (int j = 0; j < 2; j++) {
            size_t off = (size_t)m * C + c0 + j*64 + tx*4;
            float4 r;
            r.x = acc[i][j*4+0]+bb[j].x; r.y = acc[i][j*4+1]+bb[j].y;
            r.z = acc[i][j*4+2]+bb[j].z; r.w = acc[i][j*4+3]+bb[j].w;
            if (addrow) {
                float4 p = *(const float4*)(addrow + (size_t)(m & nmask)*C + c0 + j*64 + tx*4);
                r.x+=p.x; r.y+=p.y; r.z+=p.z; r.w+=p.w;
            }
            if (epi == 0) { *(float4*)(out + off) = r; continue; }
            float4 e0 = *(const float4*)(E0 + off);
            float4 e1 = *(const float4*)(E1 + off);
            float4 s = make_float4(sigm(r.x), sigm(r.y), sigm(r.z), sigm(r.w));
            float4 o4;
            if (epi == 1) {
                o4.x = s.x*e0.x+(1.f-s.x)*e1.x; o4.y = s.y*e0.y+(1.f-s.y)*e1.y;
                o4.z = s.z*e0.z+(1.f-s.z)*e1.z; o4.w = s.w*e0.w+(1.f-s.w)*e1.w;
            } else {
                o4.x = e0.x+s.x*e1.x; o4.y = e0.y+s.y*e1.y;
                o4.z = e0.z+s.z*e1.z; o4.w = e0.w+s.w*e1.w;
            }
            *(float4*)(out + off) = o4;
        }
    }
}

// ---------------- positional embeddings ------------------------------------
__global__ void posF_kernel(const float* __restrict__ pf){
    int n = blockIdx.x, c = threadIdx.x;
    int oy = n >> 6, ox = n & 63;
    float sy = oy*0.5f - 0.25f, sx = ox*0.5f - 0.25f;
    int y0 = (int)floorf(sy); float fy = sy - (float)y0;
    int x0 = (int)floorf(sx); float fx = sx - (float)x0;
    int y0c = y0<0?0:y0, y1c = (y0+1)>31?31:(y0+1);
    int x0c = x0<0?0:x0, x1c = (x0+1)>31?31:(x0+1);
    const float* p = pf + c*1024;
    float v00=p[y0c*32+x0c], v01=p[y0c*32+x1c], v10=p[y1c*32+x0c], v11=p[y1c*32+x1c];
    g_posF[n*C+c] = (1.f-fy)*((1.f-fx)*v00+fx*v01) + fy*((1.f-fx)*v10+fx*v11);
}

__global__ void posG_kernel(const float* __restrict__ pg){
    int n = blockIdx.x, c = threadIdx.x;
    int oy = n >> 4, ox = n & 15;
    const float wt[4] = {0.25f, 0.75f, 0.75f, 0.25f};
    float wy[4], wx[4]; int iy[4], ix[4];
    float swy = 0.f, swx = 0.f;
    #pragma unroll
    for (int r = 0; r < 4; r++) {
        int y = 2*oy - 1 + r;
        if (y >= 0 && y < 32) { iy[r]=y; wy[r]=wt[r]; swy+=wt[r]; } else { iy[r]=0; wy[r]=0.f; }
        int x = 2*ox - 1 + r;
        if (x >= 0 && x < 32) { ix[r]=x; wx[r]=wt[r]; swx+=wt[r]; } else { ix[r]=0; wx[r]=0.f; }
    }
    const float* p = pg + c*1024;
    float acc = 0.f;
    #pragma unroll
    for (int ry = 0; ry < 4; ry++)
        #pragma unroll
        for (int rx = 0; rx < 4; rx++)
            acc += wy[ry]*wx[rx]*p[iy[ry]*32 + ix[rx]];
    g_posG[n*C+c] = acc / (swy*swx);
}

// ---------------- pooled-LN context ----------------------------------------
__global__ void ctx_partial(){
    int c = threadIdx.x, s = blockIdx.x, b = blockIdx.y;
    size_t base = ((size_t)b*HWN + s*256)*C + c;
    float acc = 0.f;
    for (int i = 0; i < 256; i++) acc += g_u[base + (size_t)i*C];
    g_cp[(b*16+s)*C + c] = acc;
}

__global__ void ctx_final(const float* __restrict__ lng, const float* __restrict__ lnb){
    __shared__ float red[256];
    int b = blockIdx.x, c = threadIdx.x;
    float m = 0.f;
    for (int s = 0; s < 16; s++) m += g_cp[(b*16+s)*C + c];
    m *= (1.f/(float)HWN);
    red[c] = m; __syncthreads();
    for (int s = 128; s > 0; s >>= 1) { if (c < s) red[c] += red[c+s]; __syncthreads(); }
    float mu = red[0] * (1.f/(float)C); __syncthreads();
    float d = m - mu;
    red[c] = d*d; __syncthreads();
    for (int s = 128; s > 0; s >>= 1) { if (c < s) red[c] += red[c+s]; __syncthreads(); }
    float var = red[0] * (1.f/(float)C);
    g_ctx[b*C+c] = d * rsqrtf(var + 1e-5f) * lng[c] + lnb[c];
}

__global__ void ctxg_kernel(const float* __restrict__ lng, const float* __restrict__ lnb){
    __shared__ float red[256];
    int b = blockIdx.x, c = threadIdx.x;
    float m = 0.f;
    for (int n = 0; n < NG; n++) m += g_ug[((size_t)b*NG + n)*C + c];
    m *= (1.f/(float)NG);
    red[c] = m; __syncthreads();
    for (int s = 128; s > 0; s >>= 1) { if (c < s) red[c] += red[c+s]; __syncthreads(); }
    float mu = red[0] * (1.f/(float)C); __syncthreads();
    float d = m - mu;
    red[c] = d*d; __syncthreads();
    for (int s = 128; s > 0; s >>= 1) { if (c < s) red[c] += red[c+s]; __syncthreads(); }
    float var = red[0] * (1.f/(float)C);
    g_ctxg[b*C+c] = d * rsqrtf(var + 1e-5f) * lng[c] + lnb[c];
}

// cv[gate,b,c] = bias_g[c] + sum_k ctx[b,k]*Wg[(256+k),c]
__global__ void cvec_kernel(const float* __restrict__ ctx,
    const float* __restrict__ Wf, const float* __restrict__ Ww, const float* __restrict__ Wo,
    const float* __restrict__ bf, const float* __restrict__ bw, const float* __restrict__ bo,
    float* __restrict__ cv){
    __shared__ float cs[256];
    int b = blockIdx.x, gate = blockIdx.y, c = threadIdx.x;
    cs[c] = ctx[b*C+c]; __syncthreads();
    const float* Wg = (gate==0 ? Wf : (gate==1 ? Ww : Wo)) + 256*C;
    const float* bg = (gate==0 ? bf : (gate==1 ? bw : bo));
    float acc = bg[c];
    #pragma unroll 4
    for (int k = 0; k < 256; k++) acc += cs[k] * Wg[k*C + c];
    cv[(gate*BATCH + b)*C + c] = acc;
}

// ---------------- gate pointwise -------------------------------------------
__global__ void abc_kernel(float* __restrict__ da, float* __restrict__ db,
                           float* __restrict__ dc, const float* __restrict__ u, int n){
    int i = blockIdx.x*256 + threadIdx.x;
    if (i < n) {
        float a = 1.f/(1.f + expf(da[i]));   // exp(-softplus(x)) == sigmoid(-x)
        float g = sigm(db[i]);
        da[i] = a;
        db[i] = (1.f - a) * g * u[i];
        dc[i] = sigm(dc[i]);
    }
}

// ---------------- chunked bidirectional scan -------------------------------
__global__ void scan_p1(){
    int c = threadIdx.x, k = blockIdx.x % NCH, b = blockIdx.x / NCH;
    size_t base = ((size_t)b*HWN + k*CHL)*C + c;
    float P = 1.f, Sf = 0.f, Bb = 0.f;
    for (int i = 0; i < CHL; i++) {
        float av = g_a[base + (size_t)i*C], bv = g_b[base + (size_t)i*C];
        Sf = av*Sf + bv;
        Bb += P*bv;
        P *= av;
    }
    int o = (b*NCH + k)*C + c;
    g_Ag[o] = P; g_Bf[o] = Sf; g_Bb[o] = Bb;
}

__global__ void scan_p2(){
    int t = blockIdx.x*256 + threadIdx.x;
    int b = t >> 8, c = t & 255;
    float S = 0.f;
    for (int k = 0; k < NCH; k++) {
        int o = (b*NCH + k)*C + c;
        g_If[o] = S;
        S = g_Ag[o]*S + g_Bf[o];
    }
    S = 0.f;
    for (int k = NCH-1; k >= 0; k--) {
        int o = (b*NCH + k)*C + c;
        g_Ib[o] = S;
        S = g_Ag[o]*S + g_Bb[o];
    }
}

__global__ void scan_p3(){
    int c = threadIdx.x, k = blockIdx.x % NCH, b = blockIdx.x / NCH;
    size_t base = ((size_t)b*HWN + k*CHL)*C + c;
    int o = (b*NCH + k)*C + c;
    float s = g_If[o];
    for (int i = 0; i < CHL; i++) {
        size_t idx = base + (size_t)i*C;
        float av = g_a[idx], bv = g_b[idx], ov = g_o[idx], uv = g_u[idx];
        s = av*s + bv;
        g_yf[idx] = ov*s + (1.f - ov)*uv;
    }
    s = g_Ib[o];
    for (int i = CHL-1; i >= 0; i--) {
        size_t idx = base + (size_t)i*C;
        float av = g_a[idx], bv = g_b[idx], ov = g_o[idx], uv = g_u[idx];
        s = av*s + bv;
        g_yb[idx] = ov*s + (1.f - ov)*uv;
    }
}

// ---------------- global branch --------------------------------------------
__global__ void pool_kernel(const float* __restrict__ x){
    int bc = blockIdx.x, t = threadIdx.x;
    int b = bc >> 8, c = bc & 255;
    int gy = t >> 4, gx = t & 15;
    const float* xp = x + (size_t)bc*HWN + (gy*4)*64 + gx*4;
    float s = 0.f;
    #pragma unroll
    for (int iy = 0; iy < 4; iy++)
        #pragma unroll
        for (int ix = 0; ix < 4; ix++)
            s += xp[iy*64 + ix];
    g_sg[((size_t)b*NG + t)*C + c] = s * 0.0625f;
}

__global__ void scan_g(){
    int b = blockIdx.x, c = threadIdx.x;
    float s = 0.f;
    #pragma unroll 4
    for (int n = 0; n < NG; n++) {
        size_t i = ((size_t)b*NG + n)*C + c;
        float a = g_ga[i], bb = g_gb[i], o = g_go[i], u = g_ug[i];
        s = a*s + bb;
        g_yg[i] = o*s + (1.f - o)*u;
    }
}

__global__ void upsample_kernel(){
    int n = blockIdx.x, b = blockIdx.y, c = threadIdx.x;
    int oy = n >> 6, ox = n & 63;
    float sy = oy*0.25f - 0.375f, sx = ox*0.25f - 0.375f;
    int y0 = (int)floorf(sy); float fy = sy - (float)y0;
    int x0 = (int)floorf(sx); float fx = sx - (float)x0;
    int y0c = y0<0?0:y0, y1c = (y0+1)>15?15:(y0+1);
    int x0c = x0<0?0:x0, x1c = (x0+1)>15?15:(x0+1);
    const float* Y = g_yg + (size_t)b*NG*C + c;
    float v00=Y[(y0c*16+x0c)*C], v01=Y[(y0c*16+x1c)*C];
    float v10=Y[(y1c*16+x0c)*C], v11=Y[(y1c*16+x1c)*C];
    g_ygs[((size_t)b*HWN + n)*C + c] =
        (1.f-fy)*((1.f-fx)*v00+fx*v01) + fy*((1.f-fx)*v10+fx*v11);
}

// ---------------- depthwise conv -------------------------------------------
__global__ void dwconv(const float* __restrict__ x, const float* __restrict__ w,
                       const float* __restrict__ bias){
    int bc = blockIdx.x;
    int c = bc & 255;
    int h = blockIdx.y*4 + threadIdx.y;
    int wq = threadIdx.x;
    const float* xp = x + (size_t)bc*HWN;
    float kk[9];
    #pragma unroll
    for (int i = 0; i < 9; i++) kk[i] = w[c*9 + i];
    float s = bias[c];
    #pragma unroll
    for (int dy = -1; dy <= 1; dy++) {
        int yy = h + dy;
        if (yy < 0 || yy > 63) continue;
        #pragma unroll
        for (int dx = -1; dx <= 1; dx++) {
            int xx = wq + dx;
            if (xx < 0 || xx > 63) continue;
            s += xp[yy*64 + xx] * kk[(dy+1)*3 + (dx+1)];
        }
    }
    g_vmap[(size_t)bc*HWN + h*64 + wq] = s;
}

// ---------------- host ------------------------------------------------------
static float* sym(const void* s){ void* p = 0; cudaGetSymbolAddress(&p, s); return (float*)p; }

extern "C" void kernel_launch(void* const* d_in, const int* in_sizes, int n_in,
                              void* d_out, int out_size)
{
    const float* x    = (const float*)d_in[0];
    const float* Wt   = (const float*)d_in[1];
    const float* bt   = (const float*)d_in[2];
    const float* pos_fine = (const float*)d_in[3];
    const float* pos_glob = (const float*)d_in[4];
    const float* ln_g = (const float*)d_in[5];
    const float* ln_b = (const float*)d_in[6];
    const float* Wf   = (const float*)d_in[7];
    const float* bf   = (const float*)d_in[8];
    const float* Ww   = (const float*)d_in[9];
    const float* bw   = (const float*)d_in[10];
    const float* Wo   = (const float*)d_in[11];
    const float* bo   = (const float*)d_in[12];
    const float* Wr   = (const float*)d_in[13];
    const float* br   = (const float*)d_in[14];
    const float* Wgi  = (const float*)d_in[15];
    const float* bgi  = (const float*)d_in[16];
    const float* dww  = (const float*)d_in[17];
    const float* dwb  = (const float*)d_in[18];
    const float* Wl   = (const float*)d_in[19];
    const float* bl   = (const float*)d_in[20];
    const float* Wlf  = (const float*)d_in[21];
    const float* blf  = (const float*)d_in[22];
    const float* Wout = (const float*)d_in[23];
    const float* bout = (const float*)d_in[24];
    float* out = (float*)d_out;

    float* dseq  = sym(g_seq);  float* du   = sym(g_u);
    float* da    = sym(g_a);    float* db_  = sym(g_b);   float* do_  = sym(g_o);
    float* dyf   = sym(g_yf);   float* dyb  = sym(g_yb);  float* dy   = sym(g_y);
    float* dygs  = sym(g_ygs);  float* dvmap= sym(g_vmap);
    float* dv    = sym(g_v);    float* dz   = sym(g_z);   float* duout= sym(g_uout);
    float* dposF = sym(g_posF); float* dposG= sym(g_posG);
    float* dctx  = sym(g_ctx);  float* dctxg= sym(g_ctxg);
    float* dcvec = sym(g_cvec); float* dcvecg=sym(g_cvecg);
    float* dsg   = sym(g_sg);   float* dug  = sym(g_ug);
    float* dga   = sym(g_ga);   float* dgb  = sym(g_gb);  float* dgo  = sym(g_go);

    dim3 tb(32, 8);
    dim3 tg(128, 8, BATCH);
    dim3 gF(2, BATCH*HWN/BM);   // fine GEMMs: (2, 256)
    dim3 gG(2, BATCH*NG/BM);    // global GEMMs: (2, 16)

    // fine u = seq@Wt + bt + posF
    tpose<<<tg, tb>>>(x, dseq, HWN);
    posF_kernel<<<HWN, 256>>>(pos_fine);
    posG_kernel<<<NG, 256>>>(pos_glob);
    gemm<<<gF,256>>>(dseq,0,0,1, Wt, bt, dposF,4095, 0,0, 0,0, du, 0);

    // context and gates
    ctx_partial<<<dim3(16,BATCH), 256>>>();
    ctx_final<<<BATCH, 256>>>(ln_g, ln_b);
    cvec_kernel<<<dim3(BATCH,3), 256>>>(dctx, Wf,Ww,Wo, bf,bw,bo, dcvec);
    gemm<<<gF,256>>>(du,0,0,1, Wf, 0, 0,0, dcvec,            12, 0,0, da,  0);
    gemm<<<gF,256>>>(du,0,0,1, Ww, 0, 0,0, dcvec+BATCH*C,    12, 0,0, db_, 0);
    gemm<<<gF,256>>>(du,0,0,1, Wo, 0, 0,0, dcvec+2*BATCH*C,  12, 0,0, do_, 0);
    abc_kernel<<<BNC/256, 256>>>(da, db_, do_, du, BNC);

    // bidirectional scan (gates are flip-invariant)
    scan_p1<<<BATCH*NCH, 256>>>();
    scan_p2<<<8, 256>>>();
    scan_p3<<<BATCH*NCH, 256>>>();
    // y = sigmoid([u,yf,yb]@Wr+br)*yf + (1-.)*yb
    gemm<<<gF,256>>>(du,dyf,dyb,3, Wr, br, 0,0, 0,0, dyf,dyb, dy, 1);

    // global branch
    pool_kernel<<<BATCH*C, 256>>>(x);
    gemm<<<gG,256>>>(dsg,0,0,1, Wt, bt, dposG,255, 0,0, 0,0, dug, 0);
    ctxg_kernel<<<BATCH, 256>>>(ln_g, ln_b);
    cvec_kernel<<<dim3(BATCH,3), 256>>>(dctxg, Wf,Ww,Wo, bf,bw,bo, dcvecg);
    gemm<<<gG,256>>>(dug,0,0,1, Wf, 0, 0,0, dcvecg,           8, 0,0, dga, 0);
    gemm<<<gG,256>>>(dug,0,0,1, Ww, 0, 0,0, dcvecg+BATCH*C,   8, 0,0, dgb, 0);
    gemm<<<gG,256>>>(dug,0,0,1, Wo, 0, 0,0, dcvecg+2*BATCH*C, 8, 0,0, dgo, 0);
    abc_kernel<<<GNC/256, 256>>>(dga, dgb, dgo, dug, GNC);
    scan_g<<<BATCH, 256>>>();
    upsample_kernel<<<dim3(HWN,BATCH), 256>>>();

    // z = y + sigmoid([y,ygs,u]@Wgi+bgi)*ygs
    gemm<<<gF,256>>>(dy,dygs,du,3, Wgi, bgi, 0,0, 0,0, dy,dygs, dz, 2);

    // local branch: v = dwconv(x)^T @ Wl + bl ; uout = eta*v + (1-eta)*z
    dwconv<<<dim3(BATCH*C,16), dim3(64,4)>>>(x, dww, dwb);
    tpose<<<tg, tb>>>(dvmap, dseq, HWN);
    gemm<<<gF,256>>>(dseq,0,0,1, Wl, bl, 0,0, 0,0, 0,0, dv, 0);
    gemm<<<gF,256>>>(dv,dz,0,2, Wlf, blf, 0,0, 0,0, dv,dz, duout, 1);

    // out = x + (uout@Wout + bout)^T
    gemm<<<gF,256>>>(duout,0,0,1, Wout, bout, 0,0, 0,0, 0,0, du, 0);
    tpose_add<<<tg, tb>>>(du, x, out);
}

// round 13
// speedup vs baseline: 1.2215x; 1.1086x over previous
#include <cuda_runtime.h>
#include <math.h>

#define BATCH 8
#define C 256
#define HWN 4096
#define NG 256
#define BNC (BATCH*HWN*C)
#define GNC (BATCH*NG*C)
#define NCH 64
#define CHL 64
#define BM 128
#define BN 128
#define BKK 16
#define SST 132

// ---------------- scratch (device globals; no allocation allowed) ----------
__device__ float g_seq[BNC], g_u[BNC], g_a[BNC], g_b[BNC], g_o[BNC];
__device__ float g_yf[BNC], g_yb[BNC], g_y[BNC], g_ygs[BNC];
__device__ float g_vmap[BNC], g_v[BNC], g_z[BNC], g_uout[BNC];
__device__ float g_posF[HWN*C], g_posG[NG*C];
__device__ float g_ctx[BATCH*C], g_ctxg[BATCH*C];
__device__ float g_cvec[3*BATCH*C], g_cvecg[3*BATCH*C];
__device__ float g_cp[BATCH*16*C];
__device__ float g_Ag[BATCH*NCH*C], g_Bf[BATCH*NCH*C], g_Bb[BATCH*NCH*C];
__device__ float g_If[BATCH*NCH*C], g_Ib[BATCH*NCH*C];
__device__ float g_sg[GNC], g_ug[GNC], g_ga[GNC], g_gb[GNC], g_go[GNC], g_yg[GNC];

__device__ __forceinline__ float sigm(float x){ return 1.f/(1.f+expf(-x)); }

// ---------------- transpose: [B,C,N] -> [B,N,C] ----------------------------
__global__ void tpose(const float* __restrict__ in, float* __restrict__ out, int N){
    __shared__ float t[32][33];
    int b = blockIdx.z, n0 = blockIdx.x*32, c0 = blockIdx.y*32;
    int tx = threadIdx.x, ty = threadIdx.y;
    for (int i = 0; i < 32; i += 8)
        t[ty+i][tx] = in[((size_t)(b*C + c0+ty+i))*N + n0 + tx];
    __syncthreads();
    for (int i = 0; i < 32; i += 8)
        out[((size_t)(b*N + n0+ty+i))*C + c0 + tx] = t[tx][ty+i];
}

// out[B,C,N] = x[B,C,N] + t[B,N,C]^T
__global__ void tpose_add(const float* __restrict__ t, const float* __restrict__ x,
                          float* __restrict__ out){
    __shared__ float s[32][33];
    int b = blockIdx.z, n0 = blockIdx.x*32, c0 = blockIdx.y*32;
    int tx = threadIdx.x, ty = threadIdx.y;
    for (int i = 0; i < 32; i += 8)
        s[ty+i][tx] = t[((size_t)(b*HWN + n0+ty+i))*C + c0 + tx];
    __syncthreads();
    for (int i = 0; i < 32; i += 8) {
        size_t o = ((size_t)(b*C + c0+ty+i))*HWN + n0 + tx;
        out[o] = x[o] + s[tx][ty+i];
    }
}

// ---------------- GEMM: 128x128 tile, 8x8 microtile, BK=16 -----------------
// A from up to 3 row-major [M,256] segments.
// out[m,c] = sum_k A[m,k]*W[k,c] (+bias[c]) (+addrow[(m&nmask),c]) (+addb[(m>>bshift),c])
// epi: 0 raw; 1: s=sig(r), out=s*E0+(1-s)*E1; 2: s=sig(r), out=E0+s*E1
__global__ void __launch_bounds__(256, 2) gemm(
    const float* __restrict__ A0, const float* __restrict__ A1, const float* __restrict__ A2,
    int nseg, const float* __restrict__ W, const float* __restrict__ bias,
    const float* __restrict__ addrow, int nmask,
    const float* __restrict__ addb, int bshift,
    const float* __restrict__ E0, const float* __restrict__ E1,
    float* __restrict__ out, int epi)
{
    __shared__ __align__(16) float As[BKK*SST];   // As[k][m]
    __shared__ __align__(16) float Bs[BKK*SST];   // Bs[k][c]
    int m0 = blockIdx.y * BM, c0 = blockIdx.x * BN;
    int t = threadIdx.x;
    int tx = t & 15, ty = t >> 4;
    int arow = t >> 1, akq = (t & 1) * 8;         // A: 2 threads/row, 8 k each
    int brow = t >> 4, bcq = tx * 8;              // B: 16 threads/row, 8 c each
    float acc[8][8] = {};
    int K = nseg << 8;

    float4 a0, a1, b0, b1;
    {
        const float* pa = A0 + (size_t)(m0 + arow) * C + akq;
        a0 = *(const float4*)pa; a1 = *(const float4*)(pa + 4);
        const float* pb = W + (size_t)brow * C + c0 + bcq;
        b0 = *(const float4*)pb; b1 = *(const float4*)(pb + 4);
    }

    for (int k0 = 0; k0 < K; k0 += BKK) {
        // stage regs -> smem (A transposed)
        As[(akq+0)*SST + arow] = a0.x; As[(akq+1)*SST + arow] = a0.y;
        As[(akq+2)*SST + arow] = a0.z; As[(akq+3)*SST + arow] = a0.w;
        As[(akq+4)*SST + arow] = a1.x; As[(akq+5)*SST + arow] = a1.y;
        As[(akq+6)*SST + arow] = a1.z; As[(akq+7)*SST + arow] = a1.w;
        *(float4*)(Bs + brow*SST + bcq)     = b0;
        *(float4*)(Bs + brow*SST + bcq + 4) = b1;
        __syncthreads();
        if (k0 + BKK < K) {
            int kg = k0 + BKK + akq;
            const float* seg = (kg < 256) ? A0 : (kg < 512 ? A1 : A2);
            const float* pa = seg + (size_t)(m0 + arow) * C + (kg & 255);
            a0 = *(const float4*)pa; a1 = *(const float4*)(pa + 4);
            const float* pb = W + (size_t)(k0 + BKK + brow) * C + c0 + bcq;
            b0 = *(const float4*)pb; b1 = *(const float4*)(pb + 4);
        }
        #pragma unroll
        for (int kk = 0; kk < BKK; kk++) {
            float4 av0 = *(const float4*)(As + kk*SST + ty*4);
            float4 av1 = *(const float4*)(As + kk*SST + 64 + ty*4);
            float4 bv0 = *(const float4*)(Bs + kk*SST + tx*4);
            float4 bv1 = *(const float4*)(Bs + kk*SST + 64 + tx*4);
            float ar[8] = {av0.x,av0.y,av0.z,av0.w, av1.x,av1.y,av1.z,av1.w};
            float br[8] = {bv0.x,bv0.y,bv0.z,bv0.w, bv1.x,bv1.y,bv1.z,bv1.w};
            #pragma unroll
            for (int i = 0; i < 8; i++)
                #pragma unroll
                for (int j = 0; j < 8; j++)
                    acc[i][j] += ar[i] * br[j];
        }
        __syncthreads();
    }

    float4 bb[2] = {make_float4(0,0,0,0), make_float4(0,0,0,0)};
    if (bias) {
        #pragma unroll
        for (int j = 0; j < 2; j++) {
            float4 q = *(const float4*)(bias + c0 + j*64 + tx*4);
            bb[j].x+=q.x; bb[j].y+=q.y; bb[j].z+=q.z; bb[j].w+=q.w;
        }
    }
    if (addb) {
        #pragma unroll
        for (int j = 0; j < 2; j++) {
            float4 q = *(const float4*)(addb + (m0>>bshift)*C + c0 + j*64 + tx*4);
            bb[j].x+=q.x; bb[j].y+=q.y; bb[j].z+=q.z; bb[j].w+=q.w;
        }
    }
    #pragma unroll
    for (int i = 0; i < 8; i++) {
        int m = m0 + ((i < 4) ? (ty*4 + i) : (60 + ty*4 + i));
        #pragma unroll
        for (int j = 0; j < 2; j++) {
            size_t off = (size_t)m * C + c0 + j*64 + tx*4;
            float4 r;
            r.x = acc[i][j*4+0]+bb[j].x; r.y = acc[i][j*4+1]+bb[j].y;
            r.z = acc[i][j*4+2]+bb[j].z; r.w = acc[i][j*4+3]+bb[j].w;
            if (addrow) {
                float4 p = *(const float4*)(addrow + (size_t)(m & nmask)*C + c0 + j*64 + tx*4);
                r.x+=p.x; r.y+=p.y; r.z+=p.z; r.w+=p.w;
            }
            if (epi == 0) { *(float4*)(out + off) = r; continue; }
            float4 e0 = *(const float4*)(E0 + off);
            float4 e1 = *(const float4*)(E1 + off);
            float4 s = make_float4(sigm(r.x), sigm(r.y), sigm(r.z), sigm(r.w));
            float4 o4;
            if (epi == 1) {
                o4.x = s.x*e0.x+(1.f-s.x)*e1.x; o4.y = s.y*e0.y+(1.f-s.y)*e1.y;
                o4.z = s.z*e0.z+(1.f-s.z)*e1.z; o4.w = s.w*e0.w+(1.f-s.w)*e1.w;
            } else {
                o4.x = e0.x+s.x*e1.x; o4.y = e0.y+s.y*e1.y;
                o4.z = e0.z+s.z*e1.z; o4.w = e0.w+s.w*e1.w;
            }
            *(float4*)(out + off) = o4;
        }
    }
}

// ---------------- positional embeddings ------------------------------------
__global__ void posF_kernel(const float* __restrict__ pf){
    int n = blockIdx.x, c = threadIdx.x;
    int oy = n >> 6, ox = n & 63;
    float sy = oy*0.5f - 0.25f, sx = ox*0.5f - 0.25f;
    int y0 = (int)floorf(sy); float fy = sy - (float)y0;
    int x0 = (int)floorf(sx); float fx = sx - (float)x0;
    int y0c = y0<0?0:y0, y1c = (y0+1)>31?31:(y0+1);
    int x0c = x0<0?0:x0, x1c = (x0+1)>31?31:(x0+1);
    const float* p = pf + c*1024;
    float v00=p[y0c*32+x0c], v01=p[y0c*32+x1c], v10=p[y1c*32+x0c], v11=p[y1c*32+x1c];
    g_posF[n*C+c] = (1.f-fy)*((1.f-fx)*v00+fx*v01) + fy*((1.f-fx)*v10+fx*v11);
}

__global__ void posG_kernel(const float* __restrict__ pg){
    int n = blockIdx.x, c = threadIdx.x;
    int oy = n >> 4, ox = n & 15;
    const float wt[4] = {0.25f, 0.75f, 0.75f, 0.25f};
    float wy[4], wx[4]; int iy[4], ix[4];
    float swy = 0.f, swx = 0.f;
    #pragma unroll
    for (int r = 0; r < 4; r++) {
        int y = 2*oy - 1 + r;
        if (y >= 0 && y < 32) { iy[r]=y; wy[r]=wt[r]; swy+=wt[r]; } else { iy[r]=0; wy[r]=0.f; }
        int x = 2*ox - 1 + r;
        if (x >= 0 && x < 32) { ix[r]=x; wx[r]=wt[r]; swx+=wt[r]; } else { ix[r]=0; wx[r]=0.f; }
    }
    const float* p = pg + c*1024;
    float acc = 0.f;
    #pragma unroll
    for (int ry = 0; ry < 4; ry++)
        #pragma unroll
        for (int rx = 0; rx < 4; rx++)
            acc += wy[ry]*wx[rx]*p[iy[ry]*32 + ix[rx]];
    g_posG[n*C+c] = acc / (swy*swx);
}

// ---------------- pooled-LN context ----------------------------------------
__global__ void ctx_partial(){
    int c = threadIdx.x, s = blockIdx.x, b = blockIdx.y;
    size_t base = ((size_t)b*HWN + s*256)*C + c;
    float acc = 0.f;
    for (int i = 0; i < 256; i++) acc += g_u[base + (size_t)i*C];
    g_cp[(b*16+s)*C + c] = acc;
}

__global__ void ctx_final(const float* __restrict__ lng, const float* __restrict__ lnb){
    __shared__ float red[256];
    int b = blockIdx.x, c = threadIdx.x;
    float m = 0.f;
    for (int s = 0; s < 16; s++) m += g_cp[(b*16+s)*C + c];
    m *= (1.f/(float)HWN);
    red[c] = m; __syncthreads();
    for (int s = 128; s > 0; s >>= 1) { if (c < s) red[c] += red[c+s]; __syncthreads(); }
    float mu = red[0] * (1.f/(float)C); __syncthreads();
    float d = m - mu;
    red[c] = d*d; __syncthreads();
    for (int s = 128; s > 0; s >>= 1) { if (c < s) red[c] += red[c+s]; __syncthreads(); }
    float var = red[0] * (1.f/(float)C);
    g_ctx[b*C+c] = d * rsqrtf(var + 1e-5f) * lng[c] + lnb[c];
}

__global__ void ctxg_kernel(const float* __restrict__ lng, const float* __restrict__ lnb){
    __shared__ float red[256];
    int b = blockIdx.x, c = threadIdx.x;
    float m = 0.f;
    for (int n = 0; n < NG; n++) m += g_ug[((size_t)b*NG + n)*C + c];
    m *= (1.f/(float)NG);
    red[c] = m; __syncthreads();
    for (int s = 128; s > 0; s >>= 1) { if (c < s) red[c] += red[c+s]; __syncthreads(); }
    float mu = red[0] * (1.f/(float)C); __syncthreads();
    float d = m - mu;
    red[c] = d*d; __syncthreads();
    for (int s = 128; s > 0; s >>= 1) { if (c < s) red[c] += red[c+s]; __syncthreads(); }
    float var = red[0] * (1.f/(float)C);
    g_ctxg[b*C+c] = d * rsqrtf(var + 1e-5f) * lng[c] + lnb[c];
}

// cv[gate,b,c] = bias_g[c] + sum_k ctx[b,k]*Wg[(256+k),c]
__global__ void cvec_kernel(const float* __restrict__ ctx,
    const float* __restrict__ Wf, const float* __restrict__ Ww, const float* __restrict__ Wo,
    const float* __restrict__ bf, const float* __restrict__ bw, const float* __restrict__ bo,
    float* __restrict__ cv){
    __shared__ float cs[256];
    int b = blockIdx.x, gate = blockIdx.y, c = threadIdx.x;
    cs[c] = ctx[b*C+c]; __syncthreads();
    const float* Wg = (gate==0 ? Wf : (gate==1 ? Ww : Wo)) + 256*C;
    const float* bg = (gate==0 ? bf : (gate==1 ? bw : bo));
    float acc = bg[c];
    #pragma unroll 4
    for (int k = 0; k < 256; k++) acc += cs[k] * Wg[k*C + c];
    cv[(gate*BATCH + b)*C + c] = acc;
}

// ---------------- gate pointwise -------------------------------------------
__global__ void abc_kernel(float* __restrict__ da, float* __restrict__ db,
                           float* __restrict__ dc, const float* __restrict__ u, int n){
    int i = blockIdx.x*256 + threadIdx.x;
    if (i < n) {
        float a = 1.f/(1.f + expf(da[i]));   // exp(-softplus(x)) == sigmoid(-x)
        float g = sigm(db[i]);
        da[i] = a;
        db[i] = (1.f - a) * g * u[i];
        dc[i] = sigm(dc[i]);
    }
}

// ---------------- chunked bidirectional scan -------------------------------
__global__ void scan_p1(){
    int c = threadIdx.x, k = blockIdx.x % NCH, b = blockIdx.x / NCH;
    size_t base = ((size_t)b*HWN + k*CHL)*C + c;
    float P = 1.f, Sf = 0.f, Bb = 0.f;
    for (int i = 0; i < CHL; i++) {
        float av = g_a[base + (size_t)i*C], bv = g_b[base + (size_t)i*C];
        Sf = av*Sf + bv;
        Bb += P*bv;
        P *= av;
    }
    int o = (b*NCH + k)*C + c;
    g_Ag[o] = P; g_Bf[o] = Sf; g_Bb[o] = Bb;
}

__global__ void scan_p2(){
    int t = blockIdx.x*256 + threadIdx.x;
    int b = t >> 8, c = t & 255;
    float S = 0.f;
    for (int k = 0; k < NCH; k++) {
        int o = (b*NCH + k)*C + c;
        g_If[o] = S;
        S = g_Ag[o]*S + g_Bf[o];
    }
    S = 0.f;
    for (int k = NCH-1; k >= 0; k--) {
        int o = (b*NCH + k)*C + c;
        g_Ib[o] = S;
        S = g_Ag[o]*S + g_Bb[o];
    }
}

__global__ void scan_p3(){
    int c = threadIdx.x, k = blockIdx.x % NCH, b = blockIdx.x / NCH;
    size_t base = ((size_t)b*HWN + k*CHL)*C + c;
    int o = (b*NCH + k)*C + c;
    float s = g_If[o];
    for (int i = 0; i < CHL; i++) {
        size_t idx = base + (size_t)i*C;
        float av = g_a[idx], bv = g_b[idx], ov = g_o[idx], uv = g_u[idx];
        s = av*s + bv;
        g_yf[idx] = ov*s + (1.f - ov)*uv;
    }
    s = g_Ib[o];
    for (int i = CHL-1; i >= 0; i--) {
        size_t idx = base + (size_t)i*C;
        float av = g_a[idx], bv = g_b[idx], ov = g_o[idx], uv = g_u[idx];
        s = av*s + bv;
        g_yb[idx] = ov*s + (1.f - ov)*uv;
    }
}

// ---------------- global branch --------------------------------------------
__global__ void pool_kernel(const float* __restrict__ x){
    int bc = blockIdx.x, t = threadIdx.x;
    int b = bc >> 8, c = bc & 255;
    int gy = t >> 4, gx = t & 15;
    const float* xp = x + (size_t)bc*HWN + (gy*4)*64 + gx*4;
    float s = 0.f;
    #pragma unroll
    for (int iy = 0; iy < 4; iy++)
        #pragma unroll
        for (int ix = 0; ix < 4; ix++)
            s += xp[iy*64 + ix];
    g_sg[((size_t)b*NG + t)*C + c] = s * 0.0625f;
}

__global__ void scan_g(){
    int b = blockIdx.x, c = threadIdx.x;
    float s = 0.f;
    #pragma unroll 4
    for (int n = 0; n < NG; n++) {
        size_t i = ((size_t)b*NG + n)*C + c;
        float a = g_ga[i], bb = g_gb[i], o = g_go[i], u = g_ug[i];
        s = a*s + bb;
        g_yg[i] = o*s + (1.f - o)*u;
    }
}

__global__ void upsample_kernel(){
    int n = blockIdx.x, b = blockIdx.y, c = threadIdx.x;
    int oy = n >> 6, ox = n & 63;
    float sy = oy*0.25f - 0.375f, sx = ox*0.25f - 0.375f;
    int y0 = (int)floorf(sy); float fy = sy - (float)y0;
    int x0 = (int)floorf(sx); float fx = sx - (float)x0;
    int y0c = y0<0?0:y0, y1c = (y0+1)>15?15:(y0+1);
    int x0c = x0<0?0:x0, x1c = (x0+1)>15?15:(x0+1);
    const float* Y = g_yg + (size_t)b*NG*C + c;
    float v00=Y[(y0c*16+x0c)*C], v01=Y[(y0c*16+x1c)*C];
    float v10=Y[(y1c*16+x0c)*C], v11=Y[(y1c*16+x1c)*C];
    g_ygs[((size_t)b*HWN + n)*C + c] =
        (1.f-fy)*((1.f-fx)*v00+fx*v01) + fy*((1.f-fx)*v10+fx*v11);
}

// ---------------- depthwise conv -------------------------------------------
__global__ void dwconv(const float* __restrict__ x, const float* __restrict__ w,
                       const float* __restrict__ bias){
    int bc = blockIdx.x;
    int c = bc & 255;
    int h = blockIdx.y*4 + threadIdx.y;
    int wq = threadIdx.x;
    const float* xp = x + (size_t)bc*HWN;
    float kk[9];
    #pragma unroll
    for (int i = 0; i < 9; i++) kk[i] = w[c*9 + i];
    float s = bias[c];
    #pragma unroll
    for (int dy = -1; dy <= 1; dy++) {
        int yy = h + dy;
        if (yy < 0 || yy > 63) continue;
        #pragma unroll
        for (int dx = -1; dx <= 1; dx++) {
            int xx = wq + dx;
            if (xx < 0 || xx > 63) continue;
            s += xp[yy*64 + xx] * kk[(dy+1)*3 + (dx+1)];
        }
    }
    g_vmap[(size_t)bc*HWN + h*64 + wq] = s;
}

// ---------------- host ------------------------------------------------------
static float* sym(const void* s){ void* p = 0; cudaGetSymbolAddress(&p, s); return (float*)p; }

extern "C" void kernel_launch(void* const* d_in, const int* in_sizes, int n_in,
                              void* d_out, int out_size)
{
    const float* x    = (const float*)d_in[0];
    const float* Wt   = (const float*)d_in[1];
    const float* bt   = (const float*)d_in[2];
    const float* pos_fine = (const float*)d_in[3];
    const float* pos_glob = (const float*)d_in[4];
    const float* ln_g = (const float*)d_in[5];
    const float* ln_b = (const float*)d_in[6];
    const float* Wf   = (const float*)d_in[7];
    const float* bf   = (const float*)d_in[8];
    const float* Ww   = (const float*)d_in[9];
    const float* bw   = (const float*)d_in[10];
    const float* Wo   = (const float*)d_in[11];
    const float* bo   = (const float*)d_in[12];
    const float* Wr   = (const float*)d_in[13];
    const float* br   = (const float*)d_in[14];
    const float* Wgi  = (const float*)d_in[15];
    const float* bgi  = (const float*)d_in[16];
    const float* dww  = (const float*)d_in[17];
    const float* dwb  = (const float*)d_in[18];
    const float* Wl   = (const float*)d_in[19];
    const float* bl   = (const float*)d_in[20];
    const float* Wlf  = (const float*)d_in[21];
    const float* blf  = (const float*)d_in[22];
    const float* Wout = (const float*)d_in[23];
    const float* bout = (const float*)d_in[24];
    float* out = (float*)d_out;

    float* dseq  = sym(g_seq);  float* du   = sym(g_u);
    float* da    = sym(g_a);    float* db_  = sym(g_b);   float* do_  = sym(g_o);
    float* dyf   = sym(g_yf);   float* dyb  = sym(g_yb);  float* dy   = sym(g_y);
    float* dygs  = sym(g_ygs);  float* dvmap= sym(g_vmap);
    float* dv    = sym(g_v);    float* dz   = sym(g_z);   float* duout= sym(g_uout);
    float* dposF = sym(g_posF); float* dposG= sym(g_posG);
    float* dctx  = sym(g_ctx);  float* dctxg= sym(g_ctxg);
    float* dcvec = sym(g_cvec); float* dcvecg=sym(g_cvecg);
    float* dsg   = sym(g_sg);   float* dug  = sym(g_ug);
    float* dga   = sym(g_ga);   float* dgb  = sym(g_gb);  float* dgo  = sym(g_go);

    dim3 tb(32, 8);
    dim3 tg(128, 8, BATCH);
    dim3 gF(2, BATCH*HWN/BM);   // fine GEMMs: (2, 256)
    dim3 gG(2, BATCH*NG/BM);    // global GEMMs: (2, 16)

    // fine u = seq@Wt + bt + posF
    tpose<<<tg, tb>>>(x, dseq, HWN);
    posF_kernel<<<HWN, 256>>>(pos_fine);
    posG_kernel<<<NG, 256>>>(pos_glob);
    gemm<<<gF,256>>>(dseq,0,0,1, Wt, bt, dposF,4095, 0,0, 0,0, du, 0);

    // context and gates
    ctx_partial<<<dim3(16,BATCH), 256>>>();
    ctx_final<<<BATCH, 256>>>(ln_g, ln_b);
    cvec_kernel<<<dim3(BATCH,3), 256>>>(dctx, Wf,Ww,Wo, bf,bw,bo, dcvec);
    gemm<<<gF,256>>>(du,0,0,1, Wf, 0, 0,0, dcvec,            12, 0,0, da,  0);
    gemm<<<gF,256>>>(du,0,0,1, Ww, 0, 0,0, dcvec+BATCH*C,    12, 0,0, db_, 0);
    gemm<<<gF,256>>>(du,0,0,1, Wo, 0, 0,0, dcvec+2*BATCH*C,  12, 0,0, do_, 0);
    abc_kernel<<<BNC/256, 256>>>(da, db_, do_, du, BNC);

    // bidirectional scan (gates are flip-invariant)
    scan_p1<<<BATCH*NCH, 256>>>();
    scan_p2<<<8, 256>>>();
    scan_p3<<<BATCH*NCH, 256>>>();
    // y = sigmoid([u,yf,yb]@Wr+br)*yf + (1-.)*yb
    gemm<<<gF,256>>>(du,dyf,dyb,3, Wr, br, 0,0, 0,0, dyf,dyb, dy, 1);

    // global branch
    pool_kernel<<<BATCH*C, 256>>>(x);
    gemm<<<gG,256>>>(dsg,0,0,1, Wt, bt, dposG,255, 0,0, 0,0, dug, 0);
    ctxg_kernel<<<BATCH, 256>>>(ln_g, ln_b);
    cvec_kernel<<<dim3(BATCH,3), 256>>>(dctxg, Wf,Ww,Wo, bf,bw,bo, dcvecg);
    gemm<<<gG,256>>>(dug,0,0,1, Wf, 0, 0,0, dcvecg,           8, 0,0, dga, 0);
    gemm<<<gG,256>>>(dug,0,0,1, Ww, 0, 0,0, dcvecg+BATCH*C,   8, 0,0, dgb, 0);
    gemm<<<gG,256>>>(dug,0,0,1, Wo, 0, 0,0, dcvecg+2*BATCH*C, 8, 0,0, dgo, 0);
    abc_kernel<<<GNC/256, 256>>>(dga, dgb, dgo, dug, GNC);
    scan_g<<<BATCH, 256>>>();
    upsample_kernel<<<dim3(HWN,BATCH), 256>>>();

    // z = y + sigmoid([y,ygs,u]@Wgi+bgi)*ygs
    gemm<<<gF,256>>>(dy,dygs,du,3, Wgi, bgi, 0,0, 0,0, dy,dygs, dz, 2);

    // local branch: v = dwconv(x)^T @ Wl + bl ; uout = eta*v + (1-eta)*z
    dwconv<<<dim3(BATCH*C,16), dim3(64,4)>>>(x, dww, dwb);
    tpose<<<tg, tb>>>(dvmap, dseq, HWN);
    gemm<<<gF,256>>>(dseq,0,0,1, Wl, bl, 0,0, 0,0, 0,0, dv, 0);
    gemm<<<gF,256>>>(dv,dz,0,2, Wlf, blf, 0,0, 0,0, dv,dz, duout, 1);

    // out = x + (uout@Wout + bout)^T
    gemm<<<gF,256>>>(duout,0,0,1, Wout, bout, 0,0, 0,0, 0,0, du, 0);
    tpose_add<<<tg, tb>>>(du, x, out);
}